// round 6
// baseline (speedup 1.0000x reference)
#include <cuda_runtime.h>

#define BB 2
#define CIN 256
#define OCH 256
#define HH 48
#define WW 48
#define HP 54
#define WP 54
#define NPOS (HP*WP)      // 2916
#define NP2 (BB*NPOS)     // 5832
#define KS 7
#define KK 49
#define ND2 85            // symmetric offsets: dr=0,dc>=0 (7) + dr in [1,6] x dc in [-6,6] (78)

// Scratch (device globals: no allocation allowed)
__device__ float g_QK[BB*NPOS*OCH];      // [b][p][o]   ~6.0 MB
__device__ float g_V [BB*NPOS*OCH];      // [b][p][o]   ~6.0 MB
__device__ float g_CORR[ND2*NP2];        // [d][b*NPOS+p]  ~2.0 MB  (offset-major)
__device__ float g_AB[BB*NPOS*16];       // [b][p][0..6]=A(rel_h), [8..14]=B(rel_w)

// packed f32x2 FMA (Blackwell)
__device__ __forceinline__ void ffma2(unsigned long long &d, unsigned long long a, unsigned long long b) {
    asm("fma.rn.f32x2 %0, %1, %2, %0;" : "+l"(d) : "l"(a), "l"(b));
}
__device__ __forceinline__ float2 u2f(unsigned long long u) {
    float2 f; asm("mov.b64 {%0,%1}, %2;" : "=f"(f.x), "=f"(f.y) : "l"(u)); return f;
}
__device__ __forceinline__ unsigned long long dup2(float a) {
    unsigned long long r; asm("mov.b64 %0, {%1, %1};" : "=l"(r) : "f"(a)); return r;
}

// ---------------------------------------------------------------------------
// Kernel 1: fused {border-zero + 1x1 conv GEMM}.
__global__ void __launch_bounds__(256) kGemmZ(const float* __restrict__ x,
                                              const float* __restrict__ wk,
                                              const float* __restrict__ wv) {
    if (blockIdx.y == 4) {       // border zeroing
        float4 z = make_float4(0.f, 0.f, 0.f, 0.f);
        for (int idx = blockIdx.x*256 + threadIdx.x; idx < 156672; idx += 9216) {
            int c4  = idx & 63;
            int t   = idx >> 6;
            int bp  = t % 612;
            int t2  = t / 612;
            int b   = t2 & 1;
            int arr = t2 >> 1;
            int row, col;
            if (bp < 324) { int r = bp / 54; row = (r < 3) ? r : r + 48; col = bp % 54; }
            else { int u = bp - 324; row = 3 + u / 6; int c6 = u % 6; col = (c6 < 3) ? c6 : c6 + 48; }
            long off = ((long)(b*NPOS + row*54 + col)*256) + c4*4;
            if (arr == 0) *(float4*)&g_QK[off] = z;
            else          *(float4*)&g_V [off] = z;
        }
        return;
    }
    __shared__ float As[16][132];
    __shared__ float Bs[16][132];
    int tid = threadIdx.x;
    int n0 = blockIdx.x * 128;
    int m0 = blockIdx.y * 128;
    int tx = tid & 15, ty = tid >> 4;
    unsigned long long acc[8][4];
    #pragma unroll
    for (int i = 0; i < 8; i++)
        #pragma unroll
        for (int j = 0; j < 4; j++) acc[i][j] = 0ull;

    for (int kt = 0; kt < 256; kt += 16) {
        #pragma unroll
        for (int i = 0; i < 8; i++) {
            int flat = i*256 + tid;
            int k = flat >> 7, n = flat & 127;
            int nn = n0 + n;
            int b = nn / 2304, s = nn % 2304;
            As[k][n] = x[(b*256 + kt + k)*2304 + s];
        }
        #pragma unroll
        for (int i = 0; i < 8; i++) {
            int flat = i*256 + tid;
            int k = flat & 15, m = flat >> 4;
            int mm = m0 + m;
            Bs[k][m] = (mm < 256) ? wk[mm*256 + kt + k] : wv[(mm-256)*256 + kt + k];
        }
        __syncthreads();
        #pragma unroll
        for (int k = 0; k < 16; k++) {
            float4 a03 = *(const float4*)&As[k][4*ty];
            float4 a47 = *(const float4*)&As[k][64 + 4*ty];
            ulonglong2 b03 = *(const ulonglong2*)&Bs[k][4*tx];
            ulonglong2 b47 = *(const ulonglong2*)&Bs[k][64 + 4*tx];
            unsigned long long A[8] = {dup2(a03.x), dup2(a03.y), dup2(a03.z), dup2(a03.w),
                                       dup2(a47.x), dup2(a47.y), dup2(a47.z), dup2(a47.w)};
            unsigned long long B[4] = {b03.x, b03.y, b47.x, b47.y};
            #pragma unroll
            for (int i = 0; i < 8; i++)
                #pragma unroll
                for (int j = 0; j < 4; j++)
                    ffma2(acc[i][j], A[i], B[j]);
        }
        __syncthreads();
    }
    #pragma unroll
    for (int i = 0; i < 8; i++) {
        int n = n0 + ((i < 4) ? (ty*4 + i) : (64 + ty*4 + i - 4));
        int b = n / 2304, rem = n % 2304;
        int h = rem / 48, w = rem % 48;
        int pidx = (h + 3)*54 + (w + 3);
        long rowq = (long)(b*NPOS + pidx)*256;
        float2 p0 = u2f(acc[i][0]), p1 = u2f(acc[i][1]);
        float2 p2 = u2f(acc[i][2]), p3 = u2f(acc[i][3]);
        float4 va = make_float4(p0.x, p0.y, p1.x, p1.y);
        float4 vb = make_float4(p2.x, p2.y, p3.x, p3.y);
        int ma = m0 + tx*4;
        int mb = m0 + 64 + tx*4;
        if (ma < 256) *(float4*)&g_QK[rowq + ma]        = va;
        else          *(float4*)&g_V [rowq + (ma-256)]  = va;
        if (mb < 256) *(float4*)&g_QK[rowq + mb]        = vb;
        else          *(float4*)&g_V [rowq + (mb-256)]  = vb;
    }
}

// ---------------------------------------------------------------------------
// Kernel 2: CORR[d][b,p] = sum_c QK[b,p,c]*QK[b,p+d,c] for 85 symmetric offsets.
__global__ void kCorr() {
    __shared__ float4 sQ4[10*20*9];
    int b  = blockIdx.z;
    int r0 = blockIdx.y * 4;
    int c0 = blockIdx.x * 8;
    int tid = threadIdx.x;
    int pl = tid & 31;
    int wg = tid >> 5;
    int pr = pl >> 3, pc = pl & 7;
    int dbase = wg * 11;

    int doff[11];
    #pragma unroll
    for (int k = 0; k < 11; k++) {
        int t = dbase + k; if (t > 84) t = 84;
        int dr, dc;
        if (t < 7) { dr = 0; dc = t; }
        else { int u = t - 7; dr = u/13 + 1; dc = u%13 - 6; }
        doff[k] = (dr*20 + dc) * 9;
    }
    float acc[11];
    #pragma unroll
    for (int k = 0; k < 11; k++) acc[k] = 0.f;

    int own4 = (pr*20 + (pc + 6)) * 9;

    for (int cc = 0; cc < 256; cc += 32) {
        #pragma unroll
        for (int it = 0; it < 7; it++) {
            int flat = it*256 + tid;
            if (flat < 1600) {
                int pos = flat >> 3, c4 = flat & 7;
                int hr = pos / 20, hc = pos % 20;
                int gr = r0 + hr, gc = c0 - 6 + hc;
                float4 v = make_float4(0.f, 0.f, 0.f, 0.f);
                if (gr < 54 && gc >= 0 && gc < 54)
                    v = *(const float4*)&g_QK[(long)((b*NPOS + gr*54 + gc))*256 + cc + c4*4];
                sQ4[pos*9 + c4] = v;
            }
        }
        __syncthreads();
        #pragma unroll
        for (int c4 = 0; c4 < 8; c4++) {
            float4 q = sQ4[own4 + c4];
            #pragma unroll
            for (int k = 0; k < 11; k++) {
                float4 v = sQ4[own4 + doff[k] + c4];
                acc[k] += q.x*v.x + q.y*v.y + q.z*v.z + q.w*v.w;
            }
        }
        __syncthreads();
    }
    int gr = r0 + pr, gc = c0 + pc;
    if (gr < 54 && gc < 54) {
        int pg = b*NPOS + gr*54 + gc;
        #pragma unroll
        for (int k = 0; k < 11; k++) {
            int t = dbase + k;
            if (t < 85) g_CORR[t*NP2 + pg] = acc[k];
        }
    }
}

// ---------------------------------------------------------------------------
// Kernel 3: bias projections, warp-per-position, float4 coalesced.
__global__ void __launch_bounds__(256) kAB(const float* __restrict__ relh,
                                           const float* __restrict__ relw) {
    __shared__ float sR[2][7][128];
    int tid = threadIdx.x;
    for (int i = tid; i < 1792; i += 256) {
        int half = i / 896, j = i % 896;
        int r = j / 128, o = j % 128;
        sR[half][r][o] = (half == 0) ? relh[o*7 + r] : relw[o*7 + r];
    }
    __syncthreads();

    int lane = tid & 31, wid = tid >> 5;
    int p = blockIdx.x * 8 + wid;
    const float* qrow = &g_QK[(long)p*256];
    float4 q1 = *(const float4*)&qrow[4*lane];
    float4 q2 = *(const float4*)&qrow[128 + 4*lane];

    #pragma unroll
    for (int r = 0; r < 7; r++) {
        float4 rh = *(const float4*)&sR[0][r][4*lane];
        float4 rw = *(const float4*)&sR[1][r][4*lane];
        float sh = rh.x*q1.x + rh.y*q1.y + rh.z*q1.z + rh.w*q1.w;
        float sw = rw.x*q2.x + rw.y*q2.y + rw.z*q2.z + rw.w*q2.w;
        #pragma unroll
        for (int o = 16; o; o >>= 1) {
            sh += __shfl_xor_sync(0xffffffffu, sh, o);
            sw += __shfl_xor_sync(0xffffffffu, sw, o);
        }
        if (lane == 0) {
            g_AB[(long)p*16 + r]     = sh;
            g_AB[(long)p*16 + 8 + r] = sw;
        }
    }
}

// ---------------------------------------------------------------------------
// Kernel 4: 16-px row strip; fully precomputed offset tables (no per-element
// decode), combined bias table (stride 154 = 7*22, covers jpos+px), dyn smem.
// smem layout (float units):
//   S_AB49 = 0      : 49 x 154  combined bias  A[ir][jpos]+B[ic][jpos]   (30.2 KB)
//   S_S    = 7548   : 7 x 49 x 17  score chunk                          (23.3 KB)
//   S_TAB  = 13380  : 2401 packed uint {corrOff:19, biasIdx:13}          (9.6 KB)
//   S_WV   = 15784  : 49 x 17  avg weights                               (3.3 KB)
//   sABt overlays S_S during setup (16x161); sV overlays [0..10472) in phase C.
#define S_AB49 0
#define S_S    7548
#define S_TAB  13380
#define S_WV   15784
#define SMEM_FLOATS 16620   // 66480 bytes

__global__ void __launch_bounds__(256) kAttn(float* __restrict__ out) {
    extern __shared__ __align__(16) float smem[];
    float*        sAB49 = smem + S_AB49;
    float*        sS    = smem + S_S;
    unsigned int* sTab  = (unsigned int*)(smem + S_TAB);
    float*        sWv   = smem + S_WV;
    float*        sABt  = smem + S_S;      // setup-phase overlay
    float*        sV    = smem;            // phase-C overlay

    int tid = threadIdx.x;
    int w0 = blockIdx.x * 16;
    int h  = blockIdx.y;
    int b  = blockIdx.z;
    int bbase = b*NPOS;
    int blkbase = bbase + h*54 + w0;       // block-constant fold for corrOff

    // Build packed table: corrOff(19b) | biasIdx(13b)<<19   (2401 = 9*256+97)
    #pragma unroll
    for (int it = 0; it < 10; it++) {
        int e = it*256 + tid;
        if (e < 2401) {
            int ii = e / 49, jj = e % 49;
            int ir = ii / 7, ic = ii % 7, jr = jj / 7, jc = jj % 7;
            int dr = jr - ir, dc = jc - ic, r, c;
            if (dr > 0 || (dr == 0 && dc >= 0)) { r = ir; c = ic; }
            else { r = jr; c = jc; dr = -dr; dc = -dc; }
            int di = (dr == 0) ? dc : (7 + (dr-1)*13 + dc + 6);
            unsigned int corrOff = (unsigned int)(di*NP2 + blkbase + r*54 + c);
            unsigned int biasIdx = (unsigned int)(ii*154 + jr*22 + jc);
            sTab[e] = corrOff | (biasIdx << 19);
        }
    }
    // Stage bias projections transposed [e][pos] into overlay (2464 = 9*256+160)
    #pragma unroll
    for (int it = 0; it < 10; it++) {
        int i = it*256 + tid;
        if (i < 2464) {
            int e = i & 15, p2 = i >> 4;
            int r = p2 / 22, cpos = p2 % 22;
            sABt[e*161 + p2] = g_AB[(long)(bbase + (h+r)*54 + w0 + cpos)*16 + e];
        }
    }
    __syncthreads();
    // Combine into sAB49[ii*154 + jpos] = A[ir][jpos] + B[ic][jpos]  (7546 = 29*256+122)
    #pragma unroll
    for (int it = 0; it < 30; it++) {
        int i = it*256 + tid;
        if (i < 7546) {
            int ii = i / 154, jpos = i % 154;
            int ir = ii / 7, ic = ii % 7;
            sAB49[i] = sABt[ir*161 + jpos] + sABt[(8+ic)*161 + jpos];
        }
    }
    __syncthreads();

    float wacc0 = 0.f, wacc1 = 0.f, wacc2 = 0.f, wacc3 = 0.f;
    int px_b = tid >> 4, tg = tid & 15;
    int pxc  = tid & 15;                 // B1 pixel lane
    const float* pC = g_CORR + pxc;
    const float* pA = sAB49 + pxc;

    for (int chk = 0; chk < 7; chk++) {
        int ebase = chk*343;
        // B1: 5488 = 21*256 + 112 elements; q = element index within chunk
        #pragma unroll
        for (int it = 0; it < 21; it++) {
            int q = it*16 + (tid >> 4);
            unsigned int t = sTab[ebase + q];
            float s = pC[t & 0x7FFFFu] + pA[t >> 19];
            sS[q*17 + pxc] = s;
        }
        if (tid < 112) {
            int q = 21*16 + (tid >> 4);
            unsigned int t = sTab[ebase + q];
            float s = pC[t & 0x7FFFFu] + pA[t >> 19];
            sS[q*17 + pxc] = s;
        }
        __syncthreads();
        // B2: row softmax (width-16 shfl) + accumulate column sums
        #pragma unroll
        for (int rr = 0; rr < 7; rr++) {
            float v0 = sS[(rr*49 + tg     )*17 + px_b];
            float v1 = sS[(rr*49 + tg + 16)*17 + px_b];
            float v2 = sS[(rr*49 + tg + 32)*17 + px_b];
            float v3 = (tg == 0) ? sS[(rr*49 + 48)*17 + px_b] : -1e30f;
            float m = fmaxf(fmaxf(v0, v1), fmaxf(v2, v3));
            #pragma unroll
            for (int o = 8; o; o >>= 1) m = fmaxf(m, __shfl_xor_sync(0xffffffffu, m, o, 16));
            float e0 = __expf(v0 - m), e1 = __expf(v1 - m), e2 = __expf(v2 - m);
            float e3 = (tg == 0) ? __expf(v3 - m) : 0.f;
            float s = e0 + e1 + e2 + e3;
            #pragma unroll
            for (int o = 8; o; o >>= 1) s += __shfl_xor_sync(0xffffffffu, s, o, 16);
            float inv = 1.f / s;
            wacc0 += e0*inv; wacc1 += e1*inv; wacc2 += e2*inv; wacc3 += e3*inv;
        }
        __syncthreads();
    }
    sWv[(tg     )*17 + px_b] = wacc0 * (1.f/49.f);
    sWv[(tg + 16)*17 + px_b] = wacc1 * (1.f/49.f);
    sWv[(tg + 32)*17 + px_b] = wacc2 * (1.f/49.f);
    if (tg == 0) sWv[48*17 + px_b] = wacc3 * (1.f/49.f);
    __syncthreads();

    // Phase C: V gather via smem staging, 64-channel chunks
    int px = tid & 15, tc = tid >> 4;
    for (int cc = 0; cc < 256; cc += 64) {
        #pragma unroll
        for (int it = 0; it < 10; it++) {
            int i = it*256 + tid;
            if (i < 2464) {
                int f4 = i & 15, p2 = i >> 4;
                int r = p2 / 22, cpos = p2 % 22;
                float4 v = *(const float4*)&g_V[(long)(bbase + (h+r)*54 + w0 + cpos)*256 + cc + f4*4];
                *(float4*)&sV[p2*68 + f4*4] = v;
            }
        }
        __syncthreads();
        float4 acc = make_float4(0.f, 0.f, 0.f, 0.f);
        #pragma unroll
        for (int jj = 0; jj < 49; jj++) {
            int jr = jj/7, jc = jj%7;
            float w = sWv[jj*17 + px];
            float4 v = *(const float4*)&sV[(jr*22 + jc + px)*68 + tc*4];
            acc.x += w*v.x; acc.y += w*v.y; acc.z += w*v.z; acc.w += w*v.w;
        }
        int ob = ((b*256 + cc + tc*4)*48 + h)*48 + w0 + px;
        out[ob]        = acc.x;
        out[ob + 2304] = acc.y;
        out[ob + 4608] = acc.z;
        out[ob + 6912] = acc.w;
        __syncthreads();
    }
}

// ---------------------------------------------------------------------------
extern "C" void kernel_launch(void* const* d_in, const int* in_sizes, int n_in,
                              void* d_out, int out_size) {
    const float* x    = (const float*)d_in[0];
    const float* wk   = (const float*)d_in[1];
    const float* wv   = (const float*)d_in[2];
    const float* relh = (const float*)d_in[3];
    const float* relw = (const float*)d_in[4];
    float* out = (float*)d_out;

    static int smem_set = 0;
    if (!smem_set) {
        cudaFuncSetAttribute(kAttn, cudaFuncAttributeMaxDynamicSharedMemorySize,
                             SMEM_FLOATS * 4);
        smem_set = 1;
    }

    kGemmZ<<<dim3(36, 5), 256>>>(x, wk, wv);
    kCorr<<<dim3(7, 14, 2), 256>>>();
    kAB<<<729, 256>>>(relh, relw);
    kAttn<<<dim3(3, 48, 2), 256, SMEM_FLOATS * 4>>>(out);
}

// round 7
// speedup vs baseline: 1.7894x; 1.7894x over previous
#include <cuda_runtime.h>

#define BB 2
#define CIN 256
#define OCH 256
#define HH 48
#define WW 48
#define HP 54
#define WP 54
#define NPOS (HP*WP)      // 2916
#define NP2 (BB*NPOS)     // 5832
#define KS 7
#define KK 49
#define ND2 85            // symmetric offsets: dr=0,dc>=0 (7) + dr in [1,6] x dc in [-6,6] (78)

// Scratch (device globals: no allocation allowed)
__device__ float g_QK[BB*NPOS*OCH];      // [b][p][o]   ~6.0 MB
__device__ float g_V [BB*NPOS*OCH];      // [b][p][o]   ~6.0 MB
__device__ float g_CORR[ND2*NP2];        // [d][b*NPOS+p]  ~2.0 MB  (offset-major)
__device__ float g_AB[BB*NPOS*16];       // [b][p][0..6]=A(rel_h), [8..14]=B(rel_w)

// packed f32x2 FMA (Blackwell)
__device__ __forceinline__ void ffma2(unsigned long long &d, unsigned long long a, unsigned long long b) {
    asm("fma.rn.f32x2 %0, %1, %2, %0;" : "+l"(d) : "l"(a), "l"(b));
}
__device__ __forceinline__ float2 u2f(unsigned long long u) {
    float2 f; asm("mov.b64 {%0,%1}, %2;" : "=f"(f.x), "=f"(f.y) : "l"(u)); return f;
}
__device__ __forceinline__ unsigned long long dup2(float a) {
    unsigned long long r; asm("mov.b64 %0, {%1, %1};" : "=l"(r) : "f"(a)); return r;
}
// 4-byte async copy global->shared (LDGSTS): no result register, high MLP.
__device__ __forceinline__ void cpa4(unsigned int saddr, const float* g) {
    asm volatile("cp.async.ca.shared.global [%0], [%1], 4;" :: "r"(saddr), "l"(g));
}
__device__ __forceinline__ void cpa_commit_wait() {
    asm volatile("cp.async.commit_group;\ncp.async.wait_group 0;" ::: "memory");
}

// ---------------------------------------------------------------------------
// Kernel 1: fused {border-zero + 1x1 conv GEMM}.
__global__ void __launch_bounds__(256) kGemmZ(const float* __restrict__ x,
                                              const float* __restrict__ wk,
                                              const float* __restrict__ wv) {
    if (blockIdx.y == 4) {       // border zeroing
        float4 z = make_float4(0.f, 0.f, 0.f, 0.f);
        for (int idx = blockIdx.x*256 + threadIdx.x; idx < 156672; idx += 9216) {
            int c4  = idx & 63;
            int t   = idx >> 6;
            int bp  = t % 612;
            int t2  = t / 612;
            int b   = t2 & 1;
            int arr = t2 >> 1;
            int row, col;
            if (bp < 324) { int r = bp / 54; row = (r < 3) ? r : r + 48; col = bp % 54; }
            else { int u = bp - 324; row = 3 + u / 6; int c6 = u % 6; col = (c6 < 3) ? c6 : c6 + 48; }
            long off = ((long)(b*NPOS + row*54 + col)*256) + c4*4;
            if (arr == 0) *(float4*)&g_QK[off] = z;
            else          *(float4*)&g_V [off] = z;
        }
        return;
    }
    __shared__ float As[16][132];
    __shared__ float Bs[16][132];
    int tid = threadIdx.x;
    int n0 = blockIdx.x * 128;
    int m0 = blockIdx.y * 128;
    int tx = tid & 15, ty = tid >> 4;
    unsigned long long acc[8][4];
    #pragma unroll
    for (int i = 0; i < 8; i++)
        #pragma unroll
        for (int j = 0; j < 4; j++) acc[i][j] = 0ull;

    for (int kt = 0; kt < 256; kt += 16) {
        #pragma unroll
        for (int i = 0; i < 8; i++) {
            int flat = i*256 + tid;
            int k = flat >> 7, n = flat & 127;
            int nn = n0 + n;
            int b = nn / 2304, s = nn % 2304;
            As[k][n] = x[(b*256 + kt + k)*2304 + s];
        }
        #pragma unroll
        for (int i = 0; i < 8; i++) {
            int flat = i*256 + tid;
            int k = flat & 15, m = flat >> 4;
            int mm = m0 + m;
            Bs[k][m] = (mm < 256) ? wk[mm*256 + kt + k] : wv[(mm-256)*256 + kt + k];
        }
        __syncthreads();
        #pragma unroll
        for (int k = 0; k < 16; k++) {
            float4 a03 = *(const float4*)&As[k][4*ty];
            float4 a47 = *(const float4*)&As[k][64 + 4*ty];
            ulonglong2 b03 = *(const ulonglong2*)&Bs[k][4*tx];
            ulonglong2 b47 = *(const ulonglong2*)&Bs[k][64 + 4*tx];
            unsigned long long A[8] = {dup2(a03.x), dup2(a03.y), dup2(a03.z), dup2(a03.w),
                                       dup2(a47.x), dup2(a47.y), dup2(a47.z), dup2(a47.w)};
            unsigned long long B[4] = {b03.x, b03.y, b47.x, b47.y};
            #pragma unroll
            for (int i = 0; i < 8; i++)
                #pragma unroll
                for (int j = 0; j < 4; j++)
                    ffma2(acc[i][j], A[i], B[j]);
        }
        __syncthreads();
    }
    #pragma unroll
    for (int i = 0; i < 8; i++) {
        int n = n0 + ((i < 4) ? (ty*4 + i) : (64 + ty*4 + i - 4));
        int b = n / 2304, rem = n % 2304;
        int h = rem / 48, w = rem % 48;
        int pidx = (h + 3)*54 + (w + 3);
        long rowq = (long)(b*NPOS + pidx)*256;
        float2 p0 = u2f(acc[i][0]), p1 = u2f(acc[i][1]);
        float2 p2 = u2f(acc[i][2]), p3 = u2f(acc[i][3]);
        float4 va = make_float4(p0.x, p0.y, p1.x, p1.y);
        float4 vb = make_float4(p2.x, p2.y, p3.x, p3.y);
        int ma = m0 + tx*4;
        int mb = m0 + 64 + tx*4;
        if (ma < 256) *(float4*)&g_QK[rowq + ma]        = va;
        else          *(float4*)&g_V [rowq + (ma-256)]  = va;
        if (mb < 256) *(float4*)&g_QK[rowq + mb]        = vb;
        else          *(float4*)&g_V [rowq + (mb-256)]  = vb;
    }
}

// ---------------------------------------------------------------------------
// Kernel 2: CORR[d][b,p] = sum_c QK[b,p,c]*QK[b,p+d,c] for 85 symmetric offsets.
__global__ void kCorr() {
    __shared__ float4 sQ4[10*20*9];
    int b  = blockIdx.z;
    int r0 = blockIdx.y * 4;
    int c0 = blockIdx.x * 8;
    int tid = threadIdx.x;
    int pl = tid & 31;
    int wg = tid >> 5;
    int pr = pl >> 3, pc = pl & 7;
    int dbase = wg * 11;

    int doff[11];
    #pragma unroll
    for (int k = 0; k < 11; k++) {
        int t = dbase + k; if (t > 84) t = 84;
        int dr, dc;
        if (t < 7) { dr = 0; dc = t; }
        else { int u = t - 7; dr = u/13 + 1; dc = u%13 - 6; }
        doff[k] = (dr*20 + dc) * 9;
    }
    float acc[11];
    #pragma unroll
    for (int k = 0; k < 11; k++) acc[k] = 0.f;

    int own4 = (pr*20 + (pc + 6)) * 9;

    for (int cc = 0; cc < 256; cc += 32) {
        #pragma unroll
        for (int it = 0; it < 7; it++) {
            int flat = it*256 + tid;
            if (flat < 1600) {
                int pos = flat >> 3, c4 = flat & 7;
                int hr = pos / 20, hc = pos % 20;
                int gr = r0 + hr, gc = c0 - 6 + hc;
                float4 v = make_float4(0.f, 0.f, 0.f, 0.f);
                if (gr < 54 && gc >= 0 && gc < 54)
                    v = *(const float4*)&g_QK[(long)((b*NPOS + gr*54 + gc))*256 + cc + c4*4];
                sQ4[pos*9 + c4] = v;
            }
        }
        __syncthreads();
        #pragma unroll
        for (int c4 = 0; c4 < 8; c4++) {
            float4 q = sQ4[own4 + c4];
            #pragma unroll
            for (int k = 0; k < 11; k++) {
                float4 v = sQ4[own4 + doff[k] + c4];
                acc[k] += q.x*v.x + q.y*v.y + q.z*v.z + q.w*v.w;
            }
        }
        __syncthreads();
    }
    int gr = r0 + pr, gc = c0 + pc;
    if (gr < 54 && gc < 54) {
        int pg = b*NPOS + gr*54 + gc;
        #pragma unroll
        for (int k = 0; k < 11; k++) {
            int t = dbase + k;
            if (t < 85) g_CORR[t*NP2 + pg] = acc[k];
        }
    }
}

// ---------------------------------------------------------------------------
// Kernel 3: bias projections, warp-per-position, float4 coalesced.
__global__ void __launch_bounds__(256) kAB(const float* __restrict__ relh,
                                           const float* __restrict__ relw) {
    __shared__ float sR[2][7][128];
    int tid = threadIdx.x;
    for (int i = tid; i < 1792; i += 256) {
        int half = i / 896, j = i % 896;
        int r = j / 128, o = j % 128;
        sR[half][r][o] = (half == 0) ? relh[o*7 + r] : relw[o*7 + r];
    }
    __syncthreads();

    int lane = tid & 31, wid = tid >> 5;
    int p = blockIdx.x * 8 + wid;
    const float* qrow = &g_QK[(long)p*256];
    float4 q1 = *(const float4*)&qrow[4*lane];
    float4 q2 = *(const float4*)&qrow[128 + 4*lane];

    #pragma unroll
    for (int r = 0; r < 7; r++) {
        float4 rh = *(const float4*)&sR[0][r][4*lane];
        float4 rw = *(const float4*)&sR[1][r][4*lane];
        float sh = rh.x*q1.x + rh.y*q1.y + rh.z*q1.z + rh.w*q1.w;
        float sw = rw.x*q2.x + rw.y*q2.y + rw.z*q2.z + rw.w*q2.w;
        #pragma unroll
        for (int o = 16; o; o >>= 1) {
            sh += __shfl_xor_sync(0xffffffffu, sh, o);
            sw += __shfl_xor_sync(0xffffffffu, sw, o);
        }
        if (lane == 0) {
            g_AB[(long)p*16 + r]     = sh;
            g_AB[(long)p*16 + 8 + r] = sw;
        }
    }
}

// ---------------------------------------------------------------------------
// Kernel 4: 16-px row strip. B1 = cp.async (LDGSTS) of raw CORR values into
// smem (latency hidden structurally); bias added in B2 where each element is
// read exactly once. 46.1 KB STATIC smem (no attribute, no carveout games).
// Layout (float units):
//   S_ABT = 0     : 16 x 154  bias projections transposed [e][pos]  (9.86 KB)
//   S_S   = 2464  : 343 x 17  raw corr chunk                        (23.3 KB)
//   S_TAB = 8295  : 2401 uint corrOff                                (9.6 KB)
//   S_WV  = 10696 : 49 x 17   avg weights                            (3.3 KB)
//   Phase C: sV overlays [0 .. 10472) — sWv (>=10696) survives.
#define S_ABT 0
#define S_S   2464
#define S_TAB 8295
#define S_WV  10696
#define SMEM_FLOATS 11529    // 46116 bytes (static)

__global__ void __launch_bounds__(256) kAttn(float* __restrict__ out) {
    __shared__ __align__(16) float smem[SMEM_FLOATS];
    float*        sABt = smem + S_ABT;
    float*        sS   = smem + S_S;
    unsigned int* sTab = (unsigned int*)(smem + S_TAB);
    float*        sWv  = smem + S_WV;
    float*        sV   = smem;            // phase-C overlay

    int tid = threadIdx.x;
    int w0 = blockIdx.x * 16;
    int h  = blockIdx.y;
    int b  = blockIdx.z;
    int bbase = b*NPOS;
    int blkbase = bbase + h*54 + w0;      // block-constant fold for corrOff

    // Build corr-offset table (2401 = 9*256 + 97)
    #pragma unroll
    for (int it = 0; it < 10; it++) {
        int e = it*256 + tid;
        if (e < 2401) {
            int ii = e / 49, jj = e % 49;
            int ir = ii / 7, ic = ii % 7, jr = jj / 7, jc = jj % 7;
            int dr = jr - ir, dc = jc - ic, r, c;
            if (dr > 0 || (dr == 0 && dc >= 0)) { r = ir; c = ic; }
            else { r = jr; c = jc; dr = -dr; dc = -dc; }
            int di = (dr == 0) ? dc : (7 + (dr-1)*13 + dc + 6);
            sTab[e] = (unsigned int)(di*NP2 + blkbase + r*54 + c);
        }
    }
    // Stage bias projections transposed [e][pos], stride 154 (2464 = 9*256+160)
    #pragma unroll
    for (int it = 0; it < 10; it++) {
        int i = it*256 + tid;
        if (i < 2464) {
            int e = i & 15, p2 = i >> 4;
            int r = p2 / 22, cpos = p2 % 22;
            sABt[e*154 + p2] = g_AB[(long)(bbase + (h+r)*54 + w0 + cpos)*16 + e];
        }
    }
    __syncthreads();

    float wacc0 = 0.f, wacc1 = 0.f, wacc2 = 0.f, wacc3 = 0.f;
    int px_b = tid >> 4, tg = tid & 15;
    int pxc  = tid & 15, qid = tid >> 4;
    const float* pC = g_CORR + pxc;
    // per-thread column->bias-position map (jj fixed per thread in B2)
    int jm0 = (tg    / 7)*22 + (tg    % 7);
    int jm1 = ((tg+16)/7)*22 + ((tg+16) % 7);
    int jm2 = ((tg+32)/7)*22 + ((tg+32) % 7);
    // jj=48 -> 6*22+6 = 138

    for (int chk = 0; chk < 7; chk++) {
        int ebase = chk*343;
        // B1: async-copy 343x16 raw corr values into sS (21*16 + 7 tail q's)
        #pragma unroll
        for (int it = 0; it < 21; it++) {
            int q = it*16 + qid;
            unsigned int t = sTab[ebase + q];
            unsigned int saddr = (unsigned int)__cvta_generic_to_shared(&sS[q*17 + pxc]);
            cpa4(saddr, pC + t);
        }
        if (tid < 112) {
            int q = 336 + qid;
            unsigned int t = sTab[ebase + q];
            unsigned int saddr = (unsigned int)__cvta_generic_to_shared(&sS[q*17 + pxc]);
            cpa4(saddr, pC + t);
        }
        cpa_commit_wait();
        __syncthreads();
        // B2: bias add + row softmax (width-16 shfl) + accumulate column sums
        const float* pAc = sABt + chk*154 + px_b;       // A row = ir = chk
        #pragma unroll
        for (int rr = 0; rr < 7; rr++) {
            const float* pBr = sABt + (8+rr)*154 + px_b; // B row = ic = rr
            float v0 = sS[(rr*49 + tg     )*17 + px_b] + pAc[jm0] + pBr[jm0];
            float v1 = sS[(rr*49 + tg + 16)*17 + px_b] + pAc[jm1] + pBr[jm1];
            float v2 = sS[(rr*49 + tg + 32)*17 + px_b] + pAc[jm2] + pBr[jm2];
            float v3 = (tg == 0) ? (sS[(rr*49 + 48)*17 + px_b] + pAc[138] + pBr[138]) : -1e30f;
            float m = fmaxf(fmaxf(v0, v1), fmaxf(v2, v3));
            #pragma unroll
            for (int o = 8; o; o >>= 1) m = fmaxf(m, __shfl_xor_sync(0xffffffffu, m, o, 16));
            float e0 = __expf(v0 - m), e1 = __expf(v1 - m), e2 = __expf(v2 - m);
            float e3 = (tg == 0) ? __expf(v3 - m) : 0.f;
            float s = e0 + e1 + e2 + e3;
            #pragma unroll
            for (int o = 8; o; o >>= 1) s += __shfl_xor_sync(0xffffffffu, s, o, 16);
            float inv = 1.f / s;
            wacc0 += e0*inv; wacc1 += e1*inv; wacc2 += e2*inv; wacc3 += e3*inv;
        }
        __syncthreads();
    }
    sWv[(tg     )*17 + px_b] = wacc0 * (1.f/49.f);
    sWv[(tg + 16)*17 + px_b] = wacc1 * (1.f/49.f);
    sWv[(tg + 32)*17 + px_b] = wacc2 * (1.f/49.f);
    if (tg == 0) sWv[48*17 + px_b] = wacc3 * (1.f/49.f);
    __syncthreads();

    // Phase C: V gather via smem staging, 64-channel chunks
    int px = tid & 15, tc = tid >> 4;
    for (int cc = 0; cc < 256; cc += 64) {
        #pragma unroll
        for (int it = 0; it < 10; it++) {
            int i = it*256 + tid;
            if (i < 2464) {
                int f4 = i & 15, p2 = i >> 4;
                int r = p2 / 22, cpos = p2 % 22;
                float4 v = *(const float4*)&g_V[(long)(bbase + (h+r)*54 + w0 + cpos)*256 + cc + f4*4];
                *(float4*)&sV[p2*68 + f4*4] = v;
            }
        }
        __syncthreads();
        float4 acc = make_float4(0.f, 0.f, 0.f, 0.f);
        #pragma unroll
        for (int jj = 0; jj < 49; jj++) {
            int jr = jj/7, jc = jj%7;
            float w = sWv[jj*17 + px];
            float4 v = *(const float4*)&sV[(jr*22 + jc + px)*68 + tc*4];
            acc.x += w*v.x; acc.y += w*v.y; acc.z += w*v.z; acc.w += w*v.w;
        }
        int ob = ((b*256 + cc + tc*4)*48 + h)*48 + w0 + px;
        out[ob]        = acc.x;
        out[ob + 2304] = acc.y;
        out[ob + 4608] = acc.z;
        out[ob + 6912] = acc.w;
        __syncthreads();
    }
}

// ---------------------------------------------------------------------------
extern "C" void kernel_launch(void* const* d_in, const int* in_sizes, int n_in,
                              void* d_out, int out_size) {
    const float* x    = (const float*)d_in[0];
    const float* wk   = (const float*)d_in[1];
    const float* wv   = (const float*)d_in[2];
    const float* relh = (const float*)d_in[3];
    const float* relw = (const float*)d_in[4];
    float* out = (float*)d_out;

    kGemmZ<<<dim3(36, 5), 256>>>(x, wk, wv);
    kCorr<<<dim3(7, 14, 2), 256>>>();
    kAB<<<729, 256>>>(relh, relw);
    kAttn<<<dim3(3, 48, 2), 256>>>(out);
}